// round 13
// baseline (speedup 1.0000x reference)
#include <cuda_runtime.h>
#include <cuda_bf16.h>
#include <cuda_fp16.h>
#include <math_constants.h>
#include <cstdint>
#include <cstring>

// Problem constants
#define BATCH 4
#define SLEN  32768
#define C1    128
#define C2    256
#define HID   512
#define L1LEN 16384
#define L2LEN 8192
#define L3LEN 4096
#define VOCAB 2048
#define KCB   4
#define NTOK  (BATCH * KCB * L3LEN)      // 65536

// ------------------- device scratch (device-code references ONLY) -------------------
__device__ __align__(16) float g_conv1[BATCH * C1 * L1LEN];
__device__ __align__(16) float g_conv2[BATCH * C2 * L2LEN];
__device__ __align__(16) float g_feats[BATCH * L3LEN * HID];       // fp32 exact
__device__ __align__(16) float2 g_w2p[(C2 / 128) * (C1 / 8) * 56 * 64];   // packed pairs
__device__ __align__(16) float2 g_w3p[(HID / 128) * (C2 / 8) * 56 * 64];
__device__ __align__(16) __nv_bfloat16 g_fhi[BATCH * L3LEN * HID];
__device__ __align__(16) __nv_bfloat16 g_chi[KCB * VOCAB * HID];
__device__ float g_c2[KCB * VOCAB];
__device__ float g_f2[BATCH * L3LEN];
__device__ float g_cbmax[KCB];
__device__ int   g_tokens[NTOK];
__device__ int   g_cand[NTOK];
__device__ int   g_ncand;

// ==================== helpers ====================
__device__ __forceinline__ uint64_t pkdup(float v) {
    uint64_t r; asm("mov.b64 %0, {%1, %1};" : "=l"(r) : "f"(v)); return r;
}
__device__ __forceinline__ void fma2(uint64_t& c, uint64_t a, uint64_t b) {
    asm("fma.rn.f32x2 %0, %1, %2, %0;" : "+l"(c) : "l"(a), "l"(b));
}
__device__ __forceinline__ float2 upk(uint64_t v) {
    float2 f; asm("mov.b64 {%0, %1}, %2;" : "=f"(f.x), "=f"(f.y) : "l"(v)); return f;
}
__device__ __forceinline__ uint32_t smem_u32(const void* p) {
    uint32_t a;
    asm("{ .reg .u64 t; cvta.to.shared.u64 t, %1; cvt.u32.u64 %0, t; }" : "=r"(a) : "l"(p));
    return a;
}
__device__ __forceinline__ void cp_async16(uint32_t s, const void* g) {
    asm volatile("cp.async.cg.shared.global [%0], [%1], 16;" :: "r"(s), "l"(g) : "memory");
}
__device__ __forceinline__ void cp_async16z(uint32_t s, const void* g, int n) {
    asm volatile("cp.async.cg.shared.global [%0], [%1], 16, %2;" :: "r"(s), "l"(g), "r"(n) : "memory");
}
#define CP_COMMIT() asm volatile("cp.async.commit_group;" ::: "memory")
#define CP_WAIT0()  asm volatile("cp.async.wait_group 0;" ::: "memory")
#define CP_WAIT1()  asm volatile("cp.async.wait_group 1;" ::: "memory")

__device__ __forceinline__ void mma_bf16(float* c, const uint32_t* a, const uint32_t* b0, const uint32_t* b1) {
    asm volatile(
        "mma.sync.aligned.m16n8k16.row.col.f32.bf16.bf16.f32 "
        "{%0,%1,%2,%3}, {%4,%5,%6,%7}, {%8,%9}, {%0,%1,%2,%3};"
        : "+f"(c[0]), "+f"(c[1]), "+f"(c[2]), "+f"(c[3])
        : "r"(a[0]), "r"(a[1]), "r"(a[2]), "r"(a[3]), "r"(*b0), "r"(*b1));
}
__device__ __forceinline__ void ldsm_x4(uint32_t* r, uint32_t addr) {
    asm volatile("ldmatrix.sync.aligned.m8n8.x4.shared.b16 {%0,%1,%2,%3}, [%4];"
                 : "=r"(r[0]), "=r"(r[1]), "=r"(r[2]), "=r"(r[3]) : "r"(addr));
}
__device__ __forceinline__ void upd_min(float& m, float& m2, int& idx, float d, int v) {
    if (d < m)       { m2 = m; m = d; idx = v; }
    else if (d < m2) { m2 = d; }
}
__device__ __forceinline__ void merge_min(float& m, float& m2, int& idx,
                                          float om, float om2, int oidx) {
    if (om < m) { m2 = fminf(m, om2); m = om; idx = oidx; }
    else        { m2 = fminf(m2, om); }
}

// ==================== weight pack: w[co][ci][7] -> [cb][chunk][row56][pair64] ====================
template <int CI, int CO, int STAGE>
__global__ void wpack_kernel(const float* __restrict__ w) {
    float2* wp = (STAGE == 2) ? g_w2p : g_w3p;
    const int TOTAL = (CO / 128) * (CI / 8) * 56 * 64;
    int i = blockIdx.x * 256 + threadIdx.x;
    if (i >= TOTAL) return;
    int p = i & 63;
    int row = (i >> 6) % 56;
    int chunk = ((i >> 6) / 56) % (CI / 8);
    int cb = (i >> 6) / 56 / (CI / 8);
    int ci = chunk * 8 + row / 7;
    int t = row % 7;
    int c_lo = (p < 32) ? p : p + 32;
    int co_lo = cb * 128 + c_lo;
    wp[i] = make_float2(w[((size_t)co_lo * CI + ci) * 7 + t],
                        w[((size_t)(co_lo + 32) * CI + ci) * 7 + t]);
}

// ==================== conv1 ====================
__global__ __launch_bounds__(256) void conv1_fast_kernel(const float* __restrict__ x,
                                                         const float* __restrict__ w,
                                                         const float* __restrict__ bias) {
    __shared__ float a_s[136];
    int tid = threadIdx.x;
    int lane = tid & 31, lg = tid >> 5;
    int l0 = blockIdx.x * 64;
    int b = blockIdx.y;

    for (int p = tid; p < 133; p += 256) {
        int pg = 2 * l0 - 3 + p;
        a_s[p] = (pg >= 0 && pg < SLEN) ? x[(size_t)b * SLEN + pg] : 0.f;
    }
    __syncthreads();

    float wr[4][7], bv[4];
#pragma unroll
    for (int c = 0; c < 4; c++) {
        int ch = lane + 32 * c;
        bv[c] = bias[ch];
#pragma unroll
        for (int t = 0; t < 7; t++) wr[c][t] = w[ch * 7 + t];
    }

    float xv[21];
#pragma unroll
    for (int p = 0; p < 21; p++) xv[p] = a_s[16 * lg + p];

    float acc[4][8];
#pragma unroll
    for (int c = 0; c < 4; c++)
#pragma unroll
        for (int j = 0; j < 8; j++) acc[c][j] = bv[c];
#pragma unroll
    for (int t = 0; t < 7; t++) {
#pragma unroll
        for (int j = 0; j < 8; j++) {
            float xx = xv[2 * j + t];
#pragma unroll
            for (int c = 0; c < 4; c++)
                acc[c][j] = fmaf(wr[c][t], xx, acc[c][j]);
        }
    }
#pragma unroll
    for (int c = 0; c < 4; c++) {
        int ch = lane + 32 * c;
#pragma unroll
        for (int j = 0; j < 8; j++) {
            int l = l0 + lg * 8 + j;
            g_conv1[((size_t)b * C1 + ch) * L1LEN + l] = fmaxf(acc[c][j], 0.f);
        }
    }
}

// ==================== conv2/3: FFMA2 + cp.async double-buffered ====================
#define CV_INSTRIDE 168
#define CV_INSZ (8 * CV_INSTRIDE * 4)       // 5376
#define CV_WSZ  (56 * 64 * 8)               // 28672
#define CV_BUFSZ (CV_INSZ + CV_WSZ)         // 34048
#define CV_SMEM  (2 * CV_BUFSZ)             // 68096

template <int CI, int CO, int LOUT, bool RELU, bool TRANS_OUT, int STAGE>
__global__ __launch_bounds__(256, 3) void conv_fast_kernel(const float* __restrict__ bias) {
    const float*  in = (STAGE == 2) ? g_conv1 : g_conv2;
    const float2* wp = (STAGE == 2) ? g_w2p : g_w3p;
    float*       out = (STAGE == 2) ? g_conv2 : g_feats;

    const int LIN = 2 * LOUT;
    const int NCH = CI / 8;
    extern __shared__ __align__(16) char dsm[];
    uint32_t sb = smem_u32(dsm);

    int tid = threadIdx.x;
    int lane = tid & 31, lg = tid >> 5;
    int l0  = blockIdx.x * 64;
    int cb  = blockIdx.y;
    int b   = blockIdx.z;

    const int gs = 2 * l0 - 16;

    auto stage_chunk = [&](int kc, int s) {
        uint32_t base = sb + s * CV_BUFSZ;
#pragma unroll
        for (int r = 0; r < 2; r++) {
            int i = tid + r * 256;
            if (i < 320) {
                int ci = i / 40, q = i % 40;
                int gf = gs + q * 4;
                int valid = (gf >= 0 && gf + 4 <= LIN) ? 16 : 0;
                const float* src = in + ((size_t)b * CI + kc * 8 + ci) * LIN + (gf < 0 ? 0 : gf);
                cp_async16z(base + ci * (CV_INSTRIDE * 4) + q * 16, src, valid);
            }
        }
        const char* wsrc = (const char*)(wp + ((size_t)cb * NCH + kc) * 3584);
        uint32_t wdst = base + CV_INSZ;
#pragma unroll
        for (int r = 0; r < 7; r++) {
            int i = tid + r * 256;
            cp_async16(wdst + i * 16, wsrc + i * 16);
        }
        CP_COMMIT();
    };

    uint64_t acc2[2][8];
#pragma unroll
    for (int cp = 0; cp < 2; cp++)
#pragma unroll
        for (int j = 0; j < 8; j++) acc2[cp][j] = 0ull;

    stage_chunk(0, 0);

    for (int kc = 0; kc < NCH; kc++) {
        CP_WAIT0();
        __syncthreads();
        if (kc + 1 < NCH) stage_chunk(kc + 1, (kc + 1) & 1);

        const float*  in_s = (const float*)(dsm + (kc & 1) * CV_BUFSZ);
        const float2* w_s  = (const float2*)(dsm + (kc & 1) * CV_BUFSZ + CV_INSZ);

#pragma unroll
        for (int ci = 0; ci < 8; ci++) {
            const float* inrow = in_s + ci * CV_INSTRIDE + 13 + 16 * lg;
            float xvf[21];
#pragma unroll
            for (int p = 0; p < 21; p++) xvf[p] = inrow[p];

#pragma unroll
            for (int t = 0; t < 7; t++) {
                const float2* wrow = w_s + (ci * 7 + t) * 64;
                float2 w0f = wrow[lane];
                float2 w1f = wrow[32 + lane];
                uint64_t w0, w1;
                memcpy(&w0, &w0f, 8);
                memcpy(&w1, &w1f, 8);
#pragma unroll
                for (int j = 0; j < 8; j++) {
                    uint64_t xd = pkdup(xvf[2 * j + t]);
                    fma2(acc2[0][j], w0, xd);
                    fma2(acc2[1][j], w1, xd);
                }
            }
        }
        __syncthreads();
    }

#pragma unroll
    for (int cp = 0; cp < 2; cp++) {
#pragma unroll
        for (int half = 0; half < 2; half++) {
            int c = cp * 2 + half;
            int co = cb * 128 + lane + 32 * c;
            float bv = bias[co];
#pragma unroll
            for (int j = 0; j < 8; j++) {
                float2 a = upk(acc2[cp][j]);
                float r = (half == 0 ? a.x : a.y) + bv;
                if (RELU) r = fmaxf(r, 0.f);
                int l = l0 + lg * 8 + j;
                if (TRANS_OUT) {
                    size_t idx = ((size_t)b * LOUT + l) * CO + co;
                    out[idx] = r;
                    g_fhi[idx] = __float2bfloat16_rn(r);
                } else {
                    out[((size_t)b * CO + co) * LOUT + l] = r;
                }
            }
        }
    }
}

// ==================== codebook prep ====================
__global__ void split_cb_kernel(const float* __restrict__ cb) {
    int i = blockIdx.x * blockDim.x + threadIdx.x;
    if (i >= KCB * VOCAB * HID) return;
    g_chi[i] = __float2bfloat16_rn(cb[i]);
}

__global__ void c2_kernel(const float* __restrict__ cb) {
    int row = blockIdx.x * 8 + (threadIdx.x >> 5);
    int lane = threadIdx.x & 31;
    const float* p = cb + (size_t)row * HID;
    float s = 0.f;
#pragma unroll 4
    for (int h = lane; h < HID; h += 32) {
        float v = p[h];
        s = fmaf(v, v, s);
    }
#pragma unroll
    for (int off = 16; off; off >>= 1)
        s += __shfl_xor_sync(0xffffffffu, s, off);
    if (lane == 0) g_c2[row] = s;
}

__global__ void f2_kernel() {
    int row = blockIdx.x * 8 + (threadIdx.x >> 5);   // BATCH*L3LEN rows
    int lane = threadIdx.x & 31;
    const float* p = g_feats + (size_t)row * HID;
    float s = 0.f;
#pragma unroll 4
    for (int h = lane; h < HID; h += 32) {
        float v = p[h];
        s = fmaf(v, v, s);
    }
#pragma unroll
    for (int off = 16; off; off >>= 1)
        s += __shfl_xor_sync(0xffffffffu, s, off);
    if (lane == 0) g_f2[row] = s;
}

__global__ void cbmax_kernel() {
    __shared__ float red[256];
    int k = blockIdx.x;
    float m = 0.f;
    for (int v = threadIdx.x; v < VOCAB; v += 256)
        m = fmaxf(m, g_c2[k * VOCAB + v]);
    red[threadIdx.x] = m;
    __syncthreads();
    for (int s = 128; s; s >>= 1) {
        if (threadIdx.x < s) red[threadIdx.x] = fmaxf(red[threadIdx.x], red[threadIdx.x + s]);
        __syncthreads();
    }
    if (threadIdx.x == 0) { g_cbmax[k] = sqrtf(red[0]); if (k == 0) g_ncand = 0; }
}

// ==================== fused bf16 GEMM + argmin (no cross scratch) ====================
// grid (32 l-tiles, 16 bk). Block 256. A tile 128x512 bf16 resident; B streamed.
#define FS_ASTRIDE 1040
#define FS_A 0
#define FS_B (128 * FS_ASTRIDE)              // 133120
#define FS_BBUF 36864                        // 256 rows x 144B
#define FS_C2 (FS_B + 2 * FS_BBUF)           // 206848
#define FS_RED (FS_C2 + 4 * VOCAB)           // 215040
#define FS_TOTAL (FS_RED + 6144)             // 221184

#define AMB_MARGIN_UNUSED 0

__global__ __launch_bounds__(256, 1) void fused_gemm_argmin_kernel() {
    extern __shared__ __align__(16) char smem[];
    uint32_t sbase = smem_u32(smem);
    float* c2_s = (float*)(smem + FS_C2);
    float* redv = (float*)(smem + FS_RED);
    float* red2 = (float*)(smem + FS_RED + 2048);
    int*   redi = (int*)(smem + FS_RED + 4096);

    const int tid = threadIdx.x;
    const int wid = tid >> 5, lane = tid & 31;
    const int wm = wid >> 2, wn = wid & 3;
    const int g = lane >> 2, t = lane & 3;
    const int lt = blockIdx.x;
    const int bk = blockIdx.y;
    const int b = bk >> 2, k = bk & 3;
    const int l0 = lt * 128;

    const __nv_bfloat16* A  = g_fhi + ((size_t)b * L3LEN + l0) * HID;
    const __nv_bfloat16* Bm = g_chi + (size_t)k * VOCAB * HID;

    // stage A once (8192 x 16B)
    for (int i = tid; i < 8192; i += 256) {
        int r = i >> 6, q = i & 63;
        cp_async16(sbase + FS_A + r * FS_ASTRIDE + q * 16, A + (size_t)r * HID + q * 8);
    }
    auto stageB = [&](int vb, int kc, int s) {
#pragma unroll
        for (int it = 0; it < 8; it++) {
            int i = tid + it * 256;
            int r = i >> 3, q = i & 7;
            cp_async16(sbase + FS_B + s * FS_BBUF + r * 144 + q * 16,
                       Bm + (size_t)(vb * 256 + r) * HID + kc * 64 + q * 8);
        }
        CP_COMMIT();
    };
    stageB(0, 0, 0);   // group 0 = A + B(0,0)

    for (int i = tid; i < VOCAB; i += 256) c2_s[i] = g_c2[k * VOCAB + i];

    const int lrow = (lane & 7) + ((lane >> 3) & 1) * 8;
    const int lcol = (lane >> 4) * 16;
    uint32_t aad[4];
#pragma unroll
    for (int mi = 0; mi < 4; mi++)
        aad[mi] = sbase + FS_A + (wm * 64 + mi * 16 + lrow) * FS_ASTRIDE + lcol;
    uint32_t bad[2][4];
#pragma unroll
    for (int s = 0; s < 2; s++)
#pragma unroll
        for (int j = 0; j < 4; j++)
            bad[s][j] = sbase + FS_B + s * FS_BBUF + (wn * 64 + j * 16 + lrow) * 144 + lcol;

    float minv[8], min2[8];
    int   mini[8];
#pragma unroll
    for (int i = 0; i < 8; i++) { minv[i] = CUDART_INF_F; min2[i] = CUDART_INF_F; mini[i] = 0; }

    for (int vb = 0; vb < 8; vb++) {
        float acc[4][8][4];
#pragma unroll
        for (int mi = 0; mi < 4; mi++)
#pragma unroll
            for (int ni = 0; ni < 8; ni++)
#pragma unroll
                for (int j = 0; j < 4; j++) acc[mi][ni][j] = 0.f;

        for (int kc = 0; kc < 8; kc++) {
            int m = vb * 8 + kc;
            if (m < 63) {
                stageB((m + 1) >> 3, (m + 1) & 7, (m + 1) & 1);
                CP_WAIT1();
            } else {
                CP_WAIT0();
            }
            __syncthreads();
            int s = m & 1;
#pragma unroll
            for (int ks = 0; ks < 4; ks++) {
                uint32_t af[4][4], bfv[4][4];
#pragma unroll
                for (int mi = 0; mi < 4; mi++) ldsm_x4(af[mi], aad[mi] + kc * 128 + ks * 32);
#pragma unroll
                for (int j = 0; j < 4; j++)  ldsm_x4(bfv[j], bad[s][j] + ks * 32);
#pragma unroll
                for (int j = 0; j < 4; j++) {
#pragma unroll
                    for (int mi = 0; mi < 4; mi++) {
                        mma_bf16(acc[mi][2 * j],     af[mi], &bfv[j][0], &bfv[j][2]);
                        mma_bf16(acc[mi][2 * j + 1], af[mi], &bfv[j][1], &bfv[j][3]);
                    }
                }
            }
            __syncthreads();
        }

        // epilogue: dist from registers
#pragma unroll
        for (int mi = 0; mi < 4; mi++) {
#pragma unroll
            for (int half = 0; half < 2; half++) {
                int ridx = mi * 2 + half;
#pragma unroll
                for (int ni = 0; ni < 8; ni++) {
#pragma unroll
                    for (int e = 0; e < 2; e++) {
                        int col = vb * 256 + wn * 64 + ni * 8 + 2 * t + e;
                        float dist = c2_s[col] - 2.f * acc[mi][ni][half * 2 + e];
                        upd_min(minv[ridx], min2[ridx], mini[ridx], dist, col);
                    }
                }
            }
        }
    }

    // reduce over t lanes (4 lanes share each row)
#pragma unroll
    for (int off = 1; off <= 2; off <<= 1) {
#pragma unroll
        for (int i = 0; i < 8; i++) {
            float om  = __shfl_xor_sync(0xffffffffu, minv[i], off);
            float om2 = __shfl_xor_sync(0xffffffffu, min2[i], off);
            int   oi  = __shfl_xor_sync(0xffffffffu, mini[i], off);
            merge_min(minv[i], min2[i], mini[i], om, om2, oi);
        }
    }
    __syncthreads();
    if (t == 0) {
#pragma unroll
        for (int i = 0; i < 8; i++) {
            int rloc = wm * 64 + (i >> 1) * 16 + (i & 1) * 8 + g;
            redv[rloc * 4 + wn] = minv[i];
            red2[rloc * 4 + wn] = min2[i];
            redi[rloc * 4 + wn] = mini[i];
        }
    }
    __syncthreads();

    if (tid < 128) {
        float m  = redv[tid * 4 + 0];
        float m2 = red2[tid * 4 + 0];
        int   mi = redi[tid * 4 + 0];
#pragma unroll
        for (int w = 1; w < 4; w++)
            merge_min(m, m2, mi, redv[tid * 4 + w], red2[tid * 4 + w], redi[tid * 4 + w]);
        int code = bk * L3LEN + l0 + tid;
        g_tokens[code] = mi;
        float TH = 0.009f * sqrtf(g_f2[b * L3LEN + l0 + tid]) * g_cbmax[k] + 1.0f;
        if (m2 - m < TH) {
            int ci = atomicAdd(&g_ncand, 1);
            if (ci < NTOK) g_cand[ci] = code;
        }
    }
}

// ==================== exact fp32 full rescore of flagged tokens ====================
__global__ void rescore_kernel(const float* __restrict__ cb) {
    __shared__ float red_v[256];
    __shared__ int   red_i[256];
    __shared__ float f_s[HID];
    int n = g_ncand;
    if (n > NTOK) n = NTOK;
    for (int ci = blockIdx.x; ci < n; ci += gridDim.x) {
        int code = g_cand[ci];
        int l = code & (L3LEN - 1);
        int bk = code >> 12;
        int k = bk & (KCB - 1);
        int b = bk >> 2;
        __syncthreads();
        for (int h = threadIdx.x; h < HID; h += 256)
            f_s[h] = g_feats[((size_t)b * L3LEN + l) * HID + h];
        __syncthreads();
        const float* C = cb + (size_t)k * VOCAB * HID;
        float bestv = CUDART_INF_F;
        int besti = 0;
        for (int v = threadIdx.x; v < VOCAB; v += 256) {
            const float* c = C + (size_t)v * HID;
            float dot = 0.f;
#pragma unroll 8
            for (int h = 0; h < HID; h++) dot = fmaf(f_s[h], __ldg(c + h), dot);
            float d = g_c2[k * VOCAB + v] - 2.f * dot;
            if (d < bestv) { bestv = d; besti = v; }
        }
        red_v[threadIdx.x] = bestv;
        red_i[threadIdx.x] = besti;
        __syncthreads();
        for (int s = 128; s; s >>= 1) {
            if (threadIdx.x < s) {
                float ov = red_v[threadIdx.x + s];
                int   oi = red_i[threadIdx.x + s];
                if (ov < red_v[threadIdx.x] ||
                    (ov == red_v[threadIdx.x] && oi < red_i[threadIdx.x])) {
                    red_v[threadIdx.x] = ov;
                    red_i[threadIdx.x] = oi;
                }
            }
            __syncthreads();
        }
        if (threadIdx.x == 0) g_tokens[code] = red_i[0];
    }
}

// ==================== outputs ====================
__global__ void emb_kernel(const float* __restrict__ embedding, float* __restrict__ out) {
    int bl = blockIdx.x;
    int b = bl >> 12;
    int l = bl & (L3LEN - 1);
    int t0 = g_tokens[((size_t)b * KCB + 0) * L3LEN + l];
    int t1 = g_tokens[((size_t)b * KCB + 1) * L3LEN + l];
    int t2 = g_tokens[((size_t)b * KCB + 2) * L3LEN + l];
    int t3 = g_tokens[((size_t)b * KCB + 3) * L3LEN + l];
    const float4* e0 = (const float4*)(embedding + (size_t)t0 * HID);
    const float4* e1 = (const float4*)(embedding + (size_t)t1 * HID);
    const float4* e2 = (const float4*)(embedding + (size_t)t2 * HID);
    const float4* e3 = (const float4*)(embedding + (size_t)t3 * HID);
    int h = threadIdx.x;
    float4 v0 = e0[h], v1 = e1[h], v2 = e2[h], v3 = e3[h];
    float4 rr;
    rr.x = 0.25f * (v0.x + v1.x + v2.x + v3.x);
    rr.y = 0.25f * (v0.y + v1.y + v2.y + v3.y);
    rr.z = 0.25f * (v0.z + v1.z + v2.z + v3.z);
    rr.w = 0.25f * (v0.w + v1.w + v2.w + v3.w);
    ((float4*)(out + ((size_t)b * L3LEN + l) * HID))[h] = rr;
}

__global__ void tok2f_kernel(float* __restrict__ out) {
    int i = blockIdx.x * blockDim.x + threadIdx.x;
    if (i < NTOK) out[i] = (float)g_tokens[i];
}

// ==================== launch ====================
extern "C" void kernel_launch(void* const* d_in, const int* in_sizes, int n_in,
                              void* d_out, int out_size) {
    const float* audio = 0; const float* w1 = 0; const float* b1 = 0;
    const float* w2 = 0; const float* b2 = 0; const float* w3 = 0; const float* b3 = 0;
    const float* codebook = 0; const float* embedding = 0;
    for (int i = 0; i < n_in; i++) {
        const float* p = (const float*)d_in[i];
        switch (in_sizes[i]) {
            case BATCH * SLEN:      audio = p; break;
            case C1 * 1 * 7:        w1 = p; break;
            case C1:                b1 = p; break;
            case C2 * C1 * 7:       w2 = p; break;
            case C2:                b2 = p; break;
            case HID * C2 * 7:      w3 = p; break;
            case HID:               b3 = p; break;
            case KCB * VOCAB * HID: codebook = p; break;
            case VOCAB * HID:       embedding = p; break;
            default: break;
        }
    }

    cudaFuncSetAttribute(fused_gemm_argmin_kernel,
                         cudaFuncAttributeMaxDynamicSharedMemorySize, FS_TOTAL);
    cudaFuncSetAttribute(conv_fast_kernel<C1, C2, L2LEN, true, false, 2>,
                         cudaFuncAttributeMaxDynamicSharedMemorySize, CV_SMEM);
    cudaFuncSetAttribute(conv_fast_kernel<C2, HID, L3LEN, false, true, 3>,
                         cudaFuncAttributeMaxDynamicSharedMemorySize, CV_SMEM);

    // order keeps the 4th launch (ncu capture slot) = conv_fast<stage2>
    {
        dim3 grid(L1LEN / 64, BATCH);
        conv1_fast_kernel<<<grid, 256>>>(audio, w1, b1);
    }
    wpack_kernel<C1, C2, 2><<<((C2 / 128) * (C1 / 8) * 3584 + 255) / 256, 256>>>(w2);
    wpack_kernel<C2, HID, 3><<<((HID / 128) * (C2 / 8) * 3584 + 255) / 256, 256>>>(w3);
    {
        dim3 grid(L2LEN / 64, C2 / 128, BATCH);
        conv_fast_kernel<C1, C2, L2LEN, true, false, 2><<<grid, 256, CV_SMEM>>>(b2);
    }
    {
        dim3 grid(L3LEN / 64, HID / 128, BATCH);
        conv_fast_kernel<C2, HID, L3LEN, false, true, 3><<<grid, 256, CV_SMEM>>>(b3);
    }
    split_cb_kernel<<<(KCB * VOCAB * HID) / 256, 256>>>(codebook);
    c2_kernel<<<(KCB * VOCAB) / 8, 256>>>(codebook);
    f2_kernel<<<(BATCH * L3LEN) / 8, 256>>>();
    cbmax_kernel<<<KCB, 256>>>();   // also zeroes g_ncand

    {
        dim3 grid(L3LEN / 128, KCB * BATCH);
        fused_gemm_argmin_kernel<<<grid, 256, FS_TOTAL>>>();
    }
    rescore_kernel<<<1024, 256>>>(codebook);

    const int TOK = NTOK;
    const int EMB = BATCH * L3LEN * HID;
    float* out = (float*)d_out;
    if (out_size >= TOK + EMB) {
        tok2f_kernel<<<(TOK + 255) / 256, 256>>>(out);
        emb_kernel<<<BATCH * L3LEN, 128>>>(embedding, out + TOK);
    } else if (out_size >= EMB) {
        emb_kernel<<<BATCH * L3LEN, 128>>>(embedding, out);
    } else {
        tok2f_kernel<<<(TOK + 255) / 256, 256>>>(out);
    }
}